// round 7
// baseline (speedup 1.0000x reference)
#include <cuda_runtime.h>
#include <cuda_bf16.h>
#include <cstdint>

#define NHEAD 8
#define HD 128
#define BSZ 1024
#define CDIM 1024
#define NB 64
#define THREADS 1024
#define SCALE 0.08838834764831845f   // HD^-0.5

#define XPITCH 136    // bf16 elems per x row
#define WROWB 144     // bytes per W row in stage buffer (64 bf16 used)
#define QPITCH 129    // f32 elems per row

// ---- smem byte offsets ----
#define SM_XHI   0                    // 64*136*2 = 17408
#define SM_XLO   17408
#define SM_WB    34816                // 2 stage buffers * WBUF_SZ
#define WBUF_SZ  36864                // hi(128*144) + lo(128*144)
#define SM_QKV   108544               // float[3][64][QPITCH] = 99072
#define SM_TOTAL 207616
// epilogue overlays (dead regions after mma stage)
#define SM_RED   34816                // float[16][64][13] = 53248
#define SM_COEF  88064                // float[64][13]
#define SM_OUTS  0                    // float[64][QPITCH]

__device__ __nv_bfloat16 g_whi[NHEAD * 3 * HD * HD];
__device__ __nv_bfloat16 g_wlo[NHEAD * 3 * HD * HD];

__device__ __forceinline__ float rcpf(float x) {
    float y; asm("rcp.approx.ftz.f32 %0, %1;" : "=f"(y) : "f"(x)); return y;
}
__device__ __forceinline__ uint32_t smem_u32(const void* p) {
    uint32_t a;
    asm("{ .reg .u64 t; cvta.to.shared.u64 t, %1; cvt.u32.u64 %0, t; }" : "=r"(a) : "l"(p));
    return a;
}
__device__ __forceinline__ void cp_async16(uint32_t dst, const void* src) {
    asm volatile("cp.async.ca.shared.global [%0], [%1], 16;" :: "r"(dst), "l"(src) : "memory");
}
#define CP_COMMIT() asm volatile("cp.async.commit_group;" ::: "memory")
#define CP_WAIT0()  asm volatile("cp.async.wait_group 0;" ::: "memory")

__device__ __forceinline__ void mma_bf16(float c[4],
    uint32_t a0, uint32_t a1, uint32_t a2, uint32_t a3,
    uint32_t b0, uint32_t b1)
{
    asm volatile(
        "mma.sync.aligned.m16n8k16.row.col.f32.bf16.bf16.f32 "
        "{%0,%1,%2,%3}, {%4,%5,%6,%7}, {%8,%9}, {%0,%1,%2,%3};"
        : "+f"(c[0]), "+f"(c[1]), "+f"(c[2]), "+f"(c[3])
        : "r"(a0), "r"(a1), "r"(a2), "r"(a3), "r"(b0), "r"(b1));
}
__device__ __forceinline__ uint32_t bits2(__nv_bfloat162 v) {
    return *reinterpret_cast<uint32_t*>(&v);
}

// ================= prestage: fp32 W -> bf16 hi/lo =================
__global__ __launch_bounds__(256) void conv_kernel(
    const float* __restrict__ Wq, const float* __restrict__ Wkv)
{
    int i4  = blockIdx.x * 256 + threadIdx.x;
    int idx = i4 * 4;
    int hm  = idx >> 14;
    int h   = hm / 3, m = hm % 3;
    int nk  = idx & 16383;
    const float* src;
    float scl = 1.0f;
    if (m == 0)      src = Wq  + (size_t)h * 16384 + nk;
    else if (m == 1) { src = Wkv + (size_t)h * 32768 + nk; scl = SCALE; }
    else             src = Wkv + (size_t)h * 32768 + 16384 + nk;

    float4 f = *(const float4*)src;
    f.x *= scl; f.y *= scl; f.z *= scl; f.w *= scl;
    __nv_bfloat162 h01 = __floats2bfloat162_rn(f.x, f.y);
    __nv_bfloat162 h23 = __floats2bfloat162_rn(f.z, f.w);
    __nv_bfloat162 l01 = __floats2bfloat162_rn(f.x - __bfloat162float(h01.x),
                                               f.y - __bfloat162float(h01.y));
    __nv_bfloat162 l23 = __floats2bfloat162_rn(f.z - __bfloat162float(h23.x),
                                               f.w - __bfloat162float(h23.y));
    *(uint2*)(g_whi + idx) = make_uint2(bits2(h01), bits2(h23));
    *(uint2*)(g_wlo + idx) = make_uint2(bits2(l01), bits2(l23));
}

// ================= main kernel =================
__global__ __launch_bounds__(THREADS) void satt_kernel(
    const float* __restrict__ x,
    float* __restrict__ out)
{
    extern __shared__ char smem[];
    const uint32_t sbase = smem_u32(smem);
    const int tid  = threadIdx.x;
    const int wid  = tid >> 5, lane = tid & 31;
    const int g    = lane >> 2, tg = lane & 3;
    const int h    = blockIdx.y;
    const int b0   = blockIdx.x * NB;

    // ---- issue cp.async for W stage 0 (m=0, half=0) ----
    {
        const size_t wbase = (size_t)(h * 3 + 0) * 16384;
        #pragma unroll
        for (int j = 0; j < 2; ++j) {
            int c = tid + j * 1024;               // 0..2047
            int sel = c >> 10, r = (c >> 3) & 127, ch = c & 7;
            const __nv_bfloat16* src = (sel ? g_wlo : g_whi) + wbase + (size_t)r * 128 + ch * 8;
            uint32_t dst = sbase + SM_WB + sel * 18432 + r * WROWB + ch * 16;
            cp_async16(dst, src);
        }
        CP_COMMIT();
    }

    // ---- stage x (hi/lo bf16) ----
    #pragma unroll
    for (int j = 0; j < 2; ++j) {
        int i4 = tid + j * 1024;                  // float4 index over 64x128
        int b  = i4 >> 5, dq = (i4 & 31) * 4;
        float4 f = *(const float4*)(x + (size_t)(b0 + b) * CDIM + h * HD + dq);
        __nv_bfloat162 h01 = __floats2bfloat162_rn(f.x, f.y);
        __nv_bfloat162 h23 = __floats2bfloat162_rn(f.z, f.w);
        __nv_bfloat162 l01 = __floats2bfloat162_rn(f.x - __bfloat162float(h01.x),
                                                   f.y - __bfloat162float(h01.y));
        __nv_bfloat162 l23 = __floats2bfloat162_rn(f.z - __bfloat162float(h23.x),
                                                   f.w - __bfloat162float(h23.y));
        uint32_t* ph = (uint32_t*)(smem + SM_XHI + (size_t)(b * XPITCH + dq) * 2);
        uint32_t* pl = (uint32_t*)(smem + SM_XLO + (size_t)(b * XPITCH + dq) * 2);
        ph[0] = bits2(h01); ph[1] = bits2(h23);
        pl[0] = bits2(l01); pl[1] = bits2(l23);
    }

    // warp tile: M16 x N16.  mg = M group (4), ng = N group (8)
    const int mg = wid & 3;
    const int n0 = (wid >> 2) * 16;

    float acc[2][4];

    // ---- 6 pipelined stages: (matrix m, K-half) ----
    for (int s = 0; s < 6; ++s) {
        const int m = s >> 1, half = s & 1;

        CP_WAIT0();
        __syncthreads();

        if (s < 5) {   // prefetch next stage into the other buffer
            const int ns = s + 1;
            const size_t wbase = (size_t)(h * 3 + (ns >> 1)) * 16384 + (ns & 1) * 64;
            const uint32_t dbuf = sbase + SM_WB + (ns & 1) * WBUF_SZ;
            #pragma unroll
            for (int j = 0; j < 2; ++j) {
                int c = tid + j * 1024;
                int sel = c >> 10, r = (c >> 3) & 127, ch = c & 7;
                const __nv_bfloat16* src = (sel ? g_wlo : g_whi) + wbase + (size_t)r * 128 + ch * 8;
                uint32_t dst = dbuf + sel * 18432 + r * WROWB + ch * 16;
                cp_async16(dst, src);
            }
            CP_COMMIT();
        }

        if (half == 0) {
            #pragma unroll
            for (int b = 0; b < 2; ++b)
                #pragma unroll
                for (int c = 0; c < 4; ++c) acc[b][c] = 0.f;
        }

        const char* bufh = smem + SM_WB + (s & 1) * WBUF_SZ;
        const char* bufl = bufh + 18432;
        const int r = mg * 16 + g;

        #pragma unroll
        for (int ktl = 0; ktl < 4; ++ktl) {
            const int k0  = half * 64 + ktl * 16;
            const int k0l = ktl * 16;
            uint32_t A[2][4];   // [hi/lo][frag]
            {
                const char* xh = smem + SM_XHI;
                const char* xl = smem + SM_XLO;
                A[0][0] = *(const uint32_t*)(xh + (size_t)(r * XPITCH + k0 + 2*tg) * 2);
                A[0][1] = *(const uint32_t*)(xh + (size_t)((r+8) * XPITCH + k0 + 2*tg) * 2);
                A[0][2] = *(const uint32_t*)(xh + (size_t)(r * XPITCH + k0 + 8 + 2*tg) * 2);
                A[0][3] = *(const uint32_t*)(xh + (size_t)((r+8) * XPITCH + k0 + 8 + 2*tg) * 2);
                A[1][0] = *(const uint32_t*)(xl + (size_t)(r * XPITCH + k0 + 2*tg) * 2);
                A[1][1] = *(const uint32_t*)(xl + (size_t)((r+8) * XPITCH + k0 + 2*tg) * 2);
                A[1][2] = *(const uint32_t*)(xl + (size_t)(r * XPITCH + k0 + 8 + 2*tg) * 2);
                A[1][3] = *(const uint32_t*)(xl + (size_t)((r+8) * XPITCH + k0 + 8 + 2*tg) * 2);
            }
            uint32_t Bf[2][2][2];  // [Nt][hi/lo][frag]
            #pragma unroll
            for (int Nt = 0; Nt < 2; ++Nt) {
                int n = n0 + Nt * 8 + g;
                Bf[Nt][0][0] = *(const uint32_t*)(bufh + (size_t)n * WROWB + (k0l + 2*tg) * 2);
                Bf[Nt][0][1] = *(const uint32_t*)(bufh + (size_t)n * WROWB + (k0l + 8 + 2*tg) * 2);
                Bf[Nt][1][0] = *(const uint32_t*)(bufl + (size_t)n * WROWB + (k0l + 2*tg) * 2);
                Bf[Nt][1][1] = *(const uint32_t*)(bufl + (size_t)n * WROWB + (k0l + 8 + 2*tg) * 2);
            }
            #pragma unroll
            for (int Nt = 0; Nt < 2; ++Nt) {
                mma_bf16(acc[Nt], A[0][0], A[0][1], A[0][2], A[0][3],
                         Bf[Nt][0][0], Bf[Nt][0][1]);   // hi*hi
                mma_bf16(acc[Nt], A[0][0], A[0][1], A[0][2], A[0][3],
                         Bf[Nt][1][0], Bf[Nt][1][1]);   // hi*lo
                mma_bf16(acc[Nt], A[1][0], A[1][1], A[1][2], A[1][3],
                         Bf[Nt][0][0], Bf[Nt][0][1]);   // lo*hi
            }
        }

        if (half == 1) {
            float* dst = (float*)(smem + SM_QKV) + (size_t)m * NB * QPITCH;
            #pragma unroll
            for (int Nt = 0; Nt < 2; ++Nt) {
                int c = n0 + Nt * 8 + 2 * tg;
                dst[r * QPITCH + c]           = acc[Nt][0];
                dst[r * QPITCH + c + 1]       = acc[Nt][1];
                dst[(r + 8) * QPITCH + c]     = acc[Nt][2];
                dst[(r + 8) * QPITCH + c + 1] = acc[Nt][3];
            }
        }
    }
    __syncthreads();

    // ================= epilogue: separable moment softmax =================
    const float* q_s = (const float*)(smem + SM_QKV);
    const float* k_s = q_s + NB * QPITCH;
    const float* v_s = q_s + 2 * NB * QPITCH;
    float* red  = (float*)(smem + SM_RED);
    float* coef = (float*)(smem + SM_COEF);
    float* outs = (float*)(smem + SM_OUTS);

    {   // Phase A: partial moments (batch = tid&63, e-part = tid>>6 : 16 parts x 8 e)
        const int b = tid & 63, part = tid >> 6;
        float K1=0,K2=0,K3=0,K4=0,K5=0,K6=0;
        float S0=0,S1=0,S2=0,S3=0,S4=0,S5=0,S6=0;
        #pragma unroll
        for (int i = 0; i < 8; ++i) {
            int e = part * 8 + i;
            float kv = k_s[b * QPITCH + e];
            float vv = v_s[b * QPITCH + e];
            S0 += vv;
            float t = kv; K1 += t; S1 = fmaf(t, vv, S1);
            t *= kv;      K2 += t; S2 = fmaf(t, vv, S2);
            t *= kv;      K3 += t; S3 = fmaf(t, vv, S3);
            t *= kv;      K4 += t; S4 = fmaf(t, vv, S4);
            t *= kv;      K5 += t; S5 = fmaf(t, vv, S5);
            t *= kv;      K6 += t; S6 = fmaf(t, vv, S6);
        }
        float* rr = red + ((size_t)part * 64 + b) * 13;
        rr[0]=K1; rr[1]=K2; rr[2]=K3; rr[3]=K4; rr[4]=K5; rr[5]=K6;
        rr[6]=S0; rr[7]=S1; rr[8]=S2; rr[9]=S3; rr[10]=S4; rr[11]=S5; rr[12]=S6;
    }
    __syncthreads();

    if (tid < 64) {   // Phase B: combine 16 parts + fold 1/n!
        float c[13];
        #pragma unroll
        for (int j = 0; j < 13; ++j) c[j] = 0.f;
        #pragma unroll
        for (int p = 0; p < 16; ++p) {
            const float* rr = red + ((size_t)p * 64 + tid) * 13;
            #pragma unroll
            for (int j = 0; j < 13; ++j) c[j] += rr[j];
        }
        float* cc = coef + tid * 13;
        cc[0] = c[0];               cc[1] = c[1] * 0.5f;
        cc[2] = c[2] * (1.f/6.f);   cc[3] = c[3] * (1.f/24.f);
        cc[4] = c[4] * (1.f/120.f); cc[5] = c[5] * (1.f/720.f);
        cc[6] = c[6];               cc[7] = c[7];
        cc[8] = c[8] * 0.5f;        cc[9] = c[9] * (1.f/6.f);
        cc[10]= c[10]* (1.f/24.f);  cc[11]= c[11]* (1.f/120.f);
        cc[12]= c[12]* (1.f/720.f);
    }
    __syncthreads();

    {   // Phase C: Horner (batch = tid&63, 8 d's per thread)
        const int b = tid & 63, part = tid >> 6;
        const float* cc = coef + b * 13;
        const float a1=cc[0],a2=cc[1],a3=cc[2],a4=cc[3],a5=cc[4],a6=cc[5];
        const float g0=cc[6],g1=cc[7],g2=cc[8],g3=cc[9],g4=cc[10],g5=cc[11],g6=cc[12];
        #pragma unroll
        for (int i = 0; i < 8; ++i) {
            int d = part * 8 + i;
            float q = q_s[b * QPITCH + d];
            float den = fmaf(a6, q, a5);
            den = fmaf(den, q, a4); den = fmaf(den, q, a3);
            den = fmaf(den, q, a2); den = fmaf(den, q, a1);
            den = fmaf(den, q, 128.0f);
            float num = fmaf(g6, q, g5);
            num = fmaf(num, q, g4); num = fmaf(num, q, g3);
            num = fmaf(num, q, g2); num = fmaf(num, q, g1);
            num = fmaf(num, q, g0);
            outs[b * QPITCH + d] = num * rcpf(den);
        }
    }
    __syncthreads();

    {   // coalesced copy out: 1024 threads, 8 floats each
        const int b = tid >> 4, ds = (tid & 15) * 8;
        float* dst = out + (size_t)(b0 + b) * CDIM + h * HD + ds;
        #pragma unroll
        for (int j = 0; j < 2; ++j) {
            float4 v;
            v.x = outs[b * QPITCH + ds + j*4 + 0];
            v.y = outs[b * QPITCH + ds + j*4 + 1];
            v.z = outs[b * QPITCH + ds + j*4 + 2];
            v.w = outs[b * QPITCH + ds + j*4 + 3];
            *(float4*)(dst + j*4) = v;
        }
    }
}

extern "C" void kernel_launch(void* const* d_in, const int* in_sizes, int n_in,
                              void* d_out, int out_size) {
    const float* x   = (const float*)d_in[0];
    const float* Wq  = (const float*)d_in[1];
    const float* Wkv = (const float*)d_in[2];
    float* out = (float*)d_out;

    conv_kernel<<<384, 256>>>(Wq, Wkv);

    cudaFuncSetAttribute(satt_kernel, cudaFuncAttributeMaxDynamicSharedMemorySize, SM_TOTAL);
    dim3 grid(BSZ / NB, NHEAD);
    satt_kernel<<<grid, THREADS, SM_TOTAL>>>(x, out);
}

// round 8
// speedup vs baseline: 1.1250x; 1.1250x over previous
#include <cuda_runtime.h>
#include <cuda_bf16.h>
#include <cstdint>

#define NHEAD 8
#define HD 128
#define BSZ 1024
#define CDIM 1024
#define NB 64
#define THREADS 512
#define SCALE 0.08838834764831845f   // HD^-0.5

#define XPITCH 136    // bf16 elems per x row (272B = 17*16B: ldmatrix conflict-free)
#define WROWB 144     // bytes per W row (144B = 9*16B: ldmatrix conflict-free)
#define QPITCH 129    // f32 elems per row

// ---- smem byte offsets ----
#define SM_XHI   0                    // 64*136*2 = 17408
#define SM_XLO   17408
#define SM_WB    34816                // 2 stage buffers * WBUF_SZ
#define WBUF_SZ  36864                // hi(128*144) + lo(128*144)
#define SM_QKV   108544               // float[3][64][QPITCH] = 99072
#define SM_TOTAL 207616
// epilogue overlays (dead regions after mma stage)
#define SM_RED   34816                // float[8][64][13]
#define SM_COEF  61440                // float[64][13]
#define SM_OUTS  0                    // float[64][QPITCH]

__device__ __nv_bfloat16 g_whi[NHEAD * 3 * HD * HD];
__device__ __nv_bfloat16 g_wlo[NHEAD * 3 * HD * HD];

__device__ __forceinline__ float rcpf(float x) {
    float y; asm("rcp.approx.ftz.f32 %0, %1;" : "=f"(y) : "f"(x)); return y;
}
__device__ __forceinline__ uint32_t smem_u32(const void* p) {
    uint32_t a;
    asm("{ .reg .u64 t; cvta.to.shared.u64 t, %1; cvt.u32.u64 %0, t; }" : "=r"(a) : "l"(p));
    return a;
}
__device__ __forceinline__ void cp_async16(uint32_t dst, const void* src) {
    asm volatile("cp.async.ca.shared.global [%0], [%1], 16;" :: "r"(dst), "l"(src) : "memory");
}
#define CP_COMMIT() asm volatile("cp.async.commit_group;" ::: "memory")
#define CP_WAIT0()  asm volatile("cp.async.wait_group 0;" ::: "memory")

__device__ __forceinline__ void ldm_x4(uint32_t& r0, uint32_t& r1, uint32_t& r2, uint32_t& r3,
                                       uint32_t addr) {
    asm volatile("ldmatrix.sync.aligned.m8n8.x4.shared.b16 {%0,%1,%2,%3}, [%4];"
                 : "=r"(r0), "=r"(r1), "=r"(r2), "=r"(r3) : "r"(addr));
}

__device__ __forceinline__ void mma_bf16(float c[4],
    uint32_t a0, uint32_t a1, uint32_t a2, uint32_t a3,
    uint32_t b0, uint32_t b1)
{
    asm volatile(
        "mma.sync.aligned.m16n8k16.row.col.f32.bf16.bf16.f32 "
        "{%0,%1,%2,%3}, {%4,%5,%6,%7}, {%8,%9}, {%0,%1,%2,%3};"
        : "+f"(c[0]), "+f"(c[1]), "+f"(c[2]), "+f"(c[3])
        : "r"(a0), "r"(a1), "r"(a2), "r"(a3), "r"(b0), "r"(b1));
}
__device__ __forceinline__ uint32_t bits2(__nv_bfloat162 v) {
    return *reinterpret_cast<uint32_t*>(&v);
}

// ================= prestage: fp32 W -> bf16 hi/lo =================
__global__ __launch_bounds__(256) void conv_kernel(
    const float* __restrict__ Wq, const float* __restrict__ Wkv)
{
    int i4  = blockIdx.x * 256 + threadIdx.x;
    int idx = i4 * 4;
    int hm  = idx >> 14;
    int h   = hm / 3, m = hm % 3;
    int nk  = idx & 16383;
    const float* src;
    float scl = 1.0f;
    if (m == 0)      src = Wq  + (size_t)h * 16384 + nk;
    else if (m == 1) { src = Wkv + (size_t)h * 32768 + nk; scl = SCALE; }
    else             src = Wkv + (size_t)h * 32768 + 16384 + nk;

    float4 f = *(const float4*)src;
    f.x *= scl; f.y *= scl; f.z *= scl; f.w *= scl;
    __nv_bfloat162 h01 = __floats2bfloat162_rn(f.x, f.y);
    __nv_bfloat162 h23 = __floats2bfloat162_rn(f.z, f.w);
    __nv_bfloat162 l01 = __floats2bfloat162_rn(f.x - __bfloat162float(h01.x),
                                               f.y - __bfloat162float(h01.y));
    __nv_bfloat162 l23 = __floats2bfloat162_rn(f.z - __bfloat162float(h23.x),
                                               f.w - __bfloat162float(h23.y));
    *(uint2*)(g_whi + idx) = make_uint2(bits2(h01), bits2(h23));
    *(uint2*)(g_wlo + idx) = make_uint2(bits2(l01), bits2(l23));
}

// ================= main kernel =================
__global__ __launch_bounds__(THREADS) void satt_kernel(
    const float* __restrict__ x,
    float* __restrict__ out)
{
    extern __shared__ char smem[];
    const uint32_t sbase = smem_u32(smem);
    const int tid  = threadIdx.x;
    const int wid  = tid >> 5, lane = tid & 31;
    const int g    = lane >> 2, tg = lane & 3;
    const int h    = blockIdx.y;
    const int b0   = blockIdx.x * NB;

    // ---- issue cp.async for W stage 0 (m=0, half=0) ----
    {
        const size_t wbase = (size_t)(h * 3 + 0) * 16384;
        #pragma unroll
        for (int j = 0; j < 4; ++j) {
            int c = tid + j * 512;               // 0..2047
            int sel = c >> 10, r = (c >> 3) & 127, ch = c & 7;
            const __nv_bfloat16* src = (sel ? g_wlo : g_whi) + wbase + (size_t)r * 128 + ch * 8;
            uint32_t dst = sbase + SM_WB + sel * 18432 + r * WROWB + ch * 16;
            cp_async16(dst, src);
        }
        CP_COMMIT();
    }

    // ---- stage x (hi/lo bf16) ----
    #pragma unroll
    for (int j = 0; j < 4; ++j) {
        int i4 = tid + j * 512;
        int b  = i4 >> 5, dq = (i4 & 31) * 4;
        float4 f = *(const float4*)(x + (size_t)(b0 + b) * CDIM + h * HD + dq);
        __nv_bfloat162 h01 = __floats2bfloat162_rn(f.x, f.y);
        __nv_bfloat162 h23 = __floats2bfloat162_rn(f.z, f.w);
        __nv_bfloat162 l01 = __floats2bfloat162_rn(f.x - __bfloat162float(h01.x),
                                                   f.y - __bfloat162float(h01.y));
        __nv_bfloat162 l23 = __floats2bfloat162_rn(f.z - __bfloat162float(h23.x),
                                                   f.w - __bfloat162float(h23.y));
        uint32_t* ph = (uint32_t*)(smem + SM_XHI + (size_t)(b * XPITCH + dq) * 2);
        uint32_t* pl = (uint32_t*)(smem + SM_XLO + (size_t)(b * XPITCH + dq) * 2);
        ph[0] = bits2(h01); ph[1] = bits2(h23);
        pl[0] = bits2(l01); pl[1] = bits2(l23);
    }

    const int mg = wid >> 3;              // 0/1: 32-batch half
    const int n0 = (wid & 7) * 16;        // 16 output cols per warp

    // ---- per-lane ldmatrix base offsets ----
    // A tile (16 rows x 16 k): lanes 0-7 rows+0 k+0 | 8-15 rows+8 k+0 | 16-23 rows+0 k+8 | 24-31 rows+8 k+8
    const int a_row = (lane & 7) + ((lane & 8) ? 8 : 0);
    const int a_kof = (lane & 16) ? 8 : 0;
    // B tile: lanes 0-7 n+0 k+0 | 8-15 n+0 k+8 | 16-23 n+8 k+0 | 24-31 n+8 k+8
    const int b_n   = n0 + (lane & 7) + ((lane & 16) ? 8 : 0);
    const uint32_t b_lane_off = (uint32_t)b_n * WROWB + ((lane & 8) ? 16 : 0);

    float acc[2][2][4];

    // ---- 6 pipelined stages: (matrix m, K-half) ----
    for (int s = 0; s < 6; ++s) {
        const int m = s >> 1, half = s & 1;

        CP_WAIT0();
        __syncthreads();

        if (s < 5) {   // prefetch next stage into the other buffer
            const int ns = s + 1;
            const size_t wbase = (size_t)(h * 3 + (ns >> 1)) * 16384 + (ns & 1) * 64;
            const uint32_t dbuf = sbase + SM_WB + (ns & 1) * WBUF_SZ;
            #pragma unroll
            for (int j = 0; j < 4; ++j) {
                int c = tid + j * 512;
                int sel = c >> 10, r = (c >> 3) & 127, ch = c & 7;
                const __nv_bfloat16* src = (sel ? g_wlo : g_whi) + wbase + (size_t)r * 128 + ch * 8;
                uint32_t dst = dbuf + sel * 18432 + r * WROWB + ch * 16;
                cp_async16(dst, src);
            }
            CP_COMMIT();
        }

        if (half == 0) {
            #pragma unroll
            for (int a = 0; a < 2; ++a)
                #pragma unroll
                for (int b = 0; b < 2; ++b)
                    #pragma unroll
                    for (int c = 0; c < 4; ++c) acc[a][b][c] = 0.f;
        }

        const uint32_t bufh = sbase + SM_WB + (s & 1) * WBUF_SZ;
        const uint32_t bufl = bufh + 18432;

        #pragma unroll
        for (int ktl = 0; ktl < 4; ++ktl) {
            const int k0  = half * 64 + ktl * 16;   // global K for A
            const int k0l = ktl * 16;               // local K for B

            uint32_t A[2][2][4];   // [Mt][hi/lo][frag]
            #pragma unroll
            for (int Mt = 0; Mt < 2; ++Mt) {
                const uint32_t aoff =
                    (uint32_t)((mg * 32 + Mt * 16 + a_row) * XPITCH + k0 + a_kof) * 2;
                ldm_x4(A[Mt][0][0], A[Mt][0][1], A[Mt][0][2], A[Mt][0][3],
                       sbase + SM_XHI + aoff);
                ldm_x4(A[Mt][1][0], A[Mt][1][1], A[Mt][1][2], A[Mt][1][3],
                       sbase + SM_XLO + aoff);
            }
            uint32_t Bf[2][2][2];  // [hi/lo][Nt][frag]
            {
                const uint32_t boff = b_lane_off + (uint32_t)k0l * 2;
                ldm_x4(Bf[0][0][0], Bf[0][0][1], Bf[0][1][0], Bf[0][1][1], bufh + boff);
                ldm_x4(Bf[1][0][0], Bf[1][0][1], Bf[1][1][0], Bf[1][1][1], bufl + boff);
            }
            #pragma unroll
            for (int Mt = 0; Mt < 2; ++Mt)
                #pragma unroll
                for (int Nt = 0; Nt < 2; ++Nt) {
                    mma_bf16(acc[Mt][Nt], A[Mt][0][0], A[Mt][0][1], A[Mt][0][2], A[Mt][0][3],
                             Bf[0][Nt][0], Bf[0][Nt][1]);   // hi*hi
                    mma_bf16(acc[Mt][Nt], A[Mt][0][0], A[Mt][0][1], A[Mt][0][2], A[Mt][0][3],
                             Bf[1][Nt][0], Bf[1][Nt][1]);   // hi*lo
                    mma_bf16(acc[Mt][Nt], A[Mt][1][0], A[Mt][1][1], A[Mt][1][2], A[Mt][1][3],
                             Bf[0][Nt][0], Bf[0][Nt][1]);   // lo*hi
                }
        }

        if (half == 1) {
            float* dst = (float*)(smem + SM_QKV) + (size_t)m * NB * QPITCH;
            #pragma unroll
            for (int Mt = 0; Mt < 2; ++Mt)
                #pragma unroll
                for (int Nt = 0; Nt < 2; ++Nt) {
                    int r = mg * 32 + Mt * 16 + g;
                    int c = n0 + Nt * 8 + 2 * tg;
                    dst[r * QPITCH + c]           = acc[Mt][Nt][0];
                    dst[r * QPITCH + c + 1]       = acc[Mt][Nt][1];
                    dst[(r + 8) * QPITCH + c]     = acc[Mt][Nt][2];
                    dst[(r + 8) * QPITCH + c + 1] = acc[Mt][Nt][3];
                }
        }
    }
    __syncthreads();

    // ================= epilogue: separable moment softmax =================
    const float* q_s = (const float*)(smem + SM_QKV);
    const float* k_s = q_s + NB * QPITCH;
    const float* v_s = q_s + 2 * NB * QPITCH;
    float* red  = (float*)(smem + SM_RED);
    float* coef = (float*)(smem + SM_COEF);
    float* outs = (float*)(smem + SM_OUTS);

    {   // Phase A: partial moments (batch = tid&63, e-part = tid>>6)
        const int b = tid & 63, part = tid >> 6;
        float K1=0,K2=0,K3=0,K4=0,K5=0,K6=0;
        float S0=0,S1=0,S2=0,S3=0,S4=0,S5=0,S6=0;
        #pragma unroll
        for (int i = 0; i < 16; ++i) {
            int e = part * 16 + i;
            float kv = k_s[b * QPITCH + e];
            float vv = v_s[b * QPITCH + e];
            S0 += vv;
            float t = kv; K1 += t; S1 = fmaf(t, vv, S1);
            t *= kv;      K2 += t; S2 = fmaf(t, vv, S2);
            t *= kv;      K3 += t; S3 = fmaf(t, vv, S3);
            t *= kv;      K4 += t; S4 = fmaf(t, vv, S4);
            t *= kv;      K5 += t; S5 = fmaf(t, vv, S5);
            t *= kv;      K6 += t; S6 = fmaf(t, vv, S6);
        }
        float* rr = red + ((size_t)part * 64 + b) * 13;
        rr[0]=K1; rr[1]=K2; rr[2]=K3; rr[3]=K4; rr[4]=K5; rr[5]=K6;
        rr[6]=S0; rr[7]=S1; rr[8]=S2; rr[9]=S3; rr[10]=S4; rr[11]=S5; rr[12]=S6;
    }
    __syncthreads();

    if (tid < 64) {   // Phase B: combine + fold 1/n!
        float c[13];
        #pragma unroll
        for (int j = 0; j < 13; ++j) c[j] = 0.f;
        #pragma unroll
        for (int p = 0; p < 8; ++p) {
            const float* rr = red + ((size_t)p * 64 + tid) * 13;
            #pragma unroll
            for (int j = 0; j < 13; ++j) c[j] += rr[j];
        }
        float* cc = coef + tid * 13;
        cc[0] = c[0];               cc[1] = c[1] * 0.5f;
        cc[2] = c[2] * (1.f/6.f);   cc[3] = c[3] * (1.f/24.f);
        cc[4] = c[4] * (1.f/120.f); cc[5] = c[5] * (1.f/720.f);
        cc[6] = c[6];               cc[7] = c[7];
        cc[8] = c[8] * 0.5f;        cc[9] = c[9] * (1.f/6.f);
        cc[10]= c[10]* (1.f/24.f);  cc[11]= c[11]* (1.f/120.f);
        cc[12]= c[12]* (1.f/720.f);
    }
    __syncthreads();

    {   // Phase C: Horner
        const int b = tid & 63, part = tid >> 6;
        const float* cc = coef + b * 13;
        const float a1=cc[0],a2=cc[1],a3=cc[2],a4=cc[3],a5=cc[4],a6=cc[5];
        const float g0=cc[6],g1=cc[7],g2=cc[8],g3=cc[9],g4=cc[10],g5=cc[11],g6=cc[12];
        #pragma unroll
        for (int i = 0; i < 16; ++i) {
            int d = part * 16 + i;
            float q = q_s[b * QPITCH + d];
            float den = fmaf(a6, q, a5);
            den = fmaf(den, q, a4); den = fmaf(den, q, a3);
            den = fmaf(den, q, a2); den = fmaf(den, q, a1);
            den = fmaf(den, q, 128.0f);
            float num = fmaf(g6, q, g5);
            num = fmaf(num, q, g4); num = fmaf(num, q, g3);
            num = fmaf(num, q, g2); num = fmaf(num, q, g1);
            num = fmaf(num, q, g0);
            outs[b * QPITCH + d] = num * rcpf(den);
        }
    }
    __syncthreads();

    {   // coalesced copy out
        const int b = tid >> 3, ds = (tid & 7) * 16;
        float* dst = out + (size_t)(b0 + b) * CDIM + h * HD + ds;
        #pragma unroll
        for (int j = 0; j < 4; ++j) {
            float4 v;
            v.x = outs[b * QPITCH + ds + j*4 + 0];
            v.y = outs[b * QPITCH + ds + j*4 + 1];
            v.z = outs[b * QPITCH + ds + j*4 + 2];
            v.w = outs[b * QPITCH + ds + j*4 + 3];
            *(float4*)(dst + j*4) = v;
        }
    }
}

extern "C" void kernel_launch(void* const* d_in, const int* in_sizes, int n_in,
                              void* d_out, int out_size) {
    const float* x   = (const float*)d_in[0];
    const float* Wq  = (const float*)d_in[1];
    const float* Wkv = (const float*)d_in[2];
    float* out = (float*)d_out;

    conv_kernel<<<384, 256>>>(Wq, Wkv);

    cudaFuncSetAttribute(satt_kernel, cudaFuncAttributeMaxDynamicSharedMemorySize, SM_TOTAL);
    dim3 grid(BSZ / NB, NHEAD);
    satt_kernel<<<grid, THREADS, SM_TOTAL>>>(x, out);
}

// round 9
// speedup vs baseline: 1.3807x; 1.2273x over previous
#include <cuda_runtime.h>
#include <cuda_bf16.h>
#include <cstdint>

#define NHEAD 8
#define HD 128
#define BSZ 1024
#define CDIM 1024
#define NB 64
#define THREADS 512
#define SCALE 0.08838834764831845f   // HD^-0.5

#define XPITCH 136    // bf16 elems per x row (272B = 17*16B: ldmatrix conflict-free)
#define WROWB 272     // bytes per W row, full K=128 (272 = 17*16: conflict-free)
#define QPITCH 129    // f32 elems per row

// ---- smem byte offsets ----
#define SM_XHI   0                    // 64*136*2 = 17408
#define SM_XLO   17408                // -> 34816
#define SM_WB    34816                // 2 stage buffers * WBUF_SZ
#define WBUF_SZ  34816                // 128 rows * 272 B
#define SM_QKV   104448               // float[3][64][QPITCH] = 99072
#define SM_TOTAL 203520
// epilogue overlays (dead regions after mma stage)
#define SM_RED   34816                // float[8][64][13] = 26624
#define SM_COEF  61440                // float[64][13]
#define SM_OUTS  0                    // float[64][QPITCH]

__device__ __nv_bfloat16 g_whi[NHEAD * 3 * HD * HD];
__device__ float g_wvsum[NHEAD * HD];   // per-head column sums of Wv

__device__ __forceinline__ float rcpf(float x) {
    float y; asm("rcp.approx.ftz.f32 %0, %1;" : "=f"(y) : "f"(x)); return y;
}
__device__ __forceinline__ uint32_t smem_u32(const void* p) {
    uint32_t a;
    asm("{ .reg .u64 t; cvta.to.shared.u64 t, %1; cvt.u32.u64 %0, t; }" : "=r"(a) : "l"(p));
    return a;
}
__device__ __forceinline__ void cp_async16(uint32_t dst, const void* src) {
    asm volatile("cp.async.ca.shared.global [%0], [%1], 16;" :: "r"(dst), "l"(src) : "memory");
}
#define CP_COMMIT() asm volatile("cp.async.commit_group;" ::: "memory")
#define CP_WAIT0()  asm volatile("cp.async.wait_group 0;" ::: "memory")

__device__ __forceinline__ void ldm_x4(uint32_t& r0, uint32_t& r1, uint32_t& r2, uint32_t& r3,
                                       uint32_t addr) {
    asm volatile("ldmatrix.sync.aligned.m8n8.x4.shared.b16 {%0,%1,%2,%3}, [%4];"
                 : "=r"(r0), "=r"(r1), "=r"(r2), "=r"(r3) : "r"(addr));
}

__device__ __forceinline__ void mma_bf16(float c[4],
    uint32_t a0, uint32_t a1, uint32_t a2, uint32_t a3,
    uint32_t b0, uint32_t b1)
{
    asm volatile(
        "mma.sync.aligned.m16n8k16.row.col.f32.bf16.bf16.f32 "
        "{%0,%1,%2,%3}, {%4,%5,%6,%7}, {%8,%9}, {%0,%1,%2,%3};"
        : "+f"(c[0]), "+f"(c[1]), "+f"(c[2]), "+f"(c[3])
        : "r"(a0), "r"(a1), "r"(a2), "r"(a3), "r"(b0), "r"(b1));
}
__device__ __forceinline__ uint32_t bits2(__nv_bfloat162 v) {
    return *reinterpret_cast<uint32_t*>(&v);
}

// ================= prestage: fp32 W -> bf16 (+ Wv column sums) =================
__global__ __launch_bounds__(256) void conv_kernel(
    const float* __restrict__ Wq, const float* __restrict__ Wkv)
{
    if (blockIdx.x >= 384) {
        // Wv column sums for head h: wvsum[d] = sum_e Wv[h][e][d]  (fp32 exact)
        __shared__ float ps[2][128];
        const int h = blockIdx.x - 384;
        const int tid = threadIdx.x;
        const int d = tid & 127, part = tid >> 7;
        const float* src = Wkv + (size_t)h * 32768 + 16384 + d + (size_t)part * 64 * 128;
        float s = 0.f;
        #pragma unroll 16
        for (int e = 0; e < 64; ++e) s += src[(size_t)e * 128];
        ps[part][d] = s;
        __syncthreads();
        if (part == 0) g_wvsum[h * 128 + d] = ps[0][d] + ps[1][d];
        return;
    }

    int i4  = blockIdx.x * 256 + threadIdx.x;
    int idx = i4 * 4;
    int hm  = idx >> 14;
    int h   = hm / 3, m = hm % 3;
    int nk  = idx & 16383;
    const float* src;
    float scl = 1.0f;
    if (m == 0)      src = Wq  + (size_t)h * 16384 + nk;
    else if (m == 1) { src = Wkv + (size_t)h * 32768 + nk; scl = SCALE; }
    else             src = Wkv + (size_t)h * 32768 + 16384 + nk;

    float4 f = *(const float4*)src;
    f.x *= scl; f.y *= scl; f.z *= scl; f.w *= scl;
    __nv_bfloat162 h01 = __floats2bfloat162_rn(f.x, f.y);
    __nv_bfloat162 h23 = __floats2bfloat162_rn(f.z, f.w);
    *(uint2*)(g_whi + idx) = make_uint2(bits2(h01), bits2(h23));
}

// ================= main kernel =================
__global__ __launch_bounds__(THREADS) void satt_kernel(
    const float* __restrict__ x,
    float* __restrict__ out)
{
    extern __shared__ char smem[];
    const uint32_t sbase = smem_u32(smem);
    const int tid  = threadIdx.x;
    const int wid  = tid >> 5, lane = tid & 31;
    const int g    = lane >> 2, tg = lane & 3;
    const int h    = blockIdx.y;
    const int b0   = blockIdx.x * NB;

    // ---- issue cp.async for W stage 0 (matrix 0, full K) ----
    {
        const __nv_bfloat16* wsrc = g_whi + (size_t)(h * 3 + 0) * 16384;
        #pragma unroll
        for (int j = 0; j < 4; ++j) {
            int c = tid + j * 512;               // 0..2047
            int r = c >> 4, ch = c & 15;
            cp_async16(sbase + SM_WB + r * WROWB + ch * 16,
                       wsrc + (size_t)r * 128 + ch * 8);
        }
        CP_COMMIT();
    }

    // ---- stage x (hi/lo bf16) ----
    #pragma unroll
    for (int j = 0; j < 4; ++j) {
        int i4 = tid + j * 512;
        int b  = i4 >> 5, dq = (i4 & 31) * 4;
        float4 f = *(const float4*)(x + (size_t)(b0 + b) * CDIM + h * HD + dq);
        __nv_bfloat162 h01 = __floats2bfloat162_rn(f.x, f.y);
        __nv_bfloat162 h23 = __floats2bfloat162_rn(f.z, f.w);
        __nv_bfloat162 l01 = __floats2bfloat162_rn(f.x - __bfloat162float(h01.x),
                                                   f.y - __bfloat162float(h01.y));
        __nv_bfloat162 l23 = __floats2bfloat162_rn(f.z - __bfloat162float(h23.x),
                                                   f.w - __bfloat162float(h23.y));
        uint32_t* ph = (uint32_t*)(smem + SM_XHI + (size_t)(b * XPITCH + dq) * 2);
        uint32_t* pl = (uint32_t*)(smem + SM_XLO + (size_t)(b * XPITCH + dq) * 2);
        ph[0] = bits2(h01); ph[1] = bits2(h23);
        pl[0] = bits2(l01); pl[1] = bits2(l23);
    }

    const int mg = wid >> 3;              // 0/1: 32-batch half
    const int n0 = (wid & 7) * 16;        // 16 output cols per warp

    // ---- per-lane ldmatrix base offsets ----
    const int a_row = (lane & 7) + ((lane & 8) ? 8 : 0);
    const int a_kof = (lane & 16) ? 8 : 0;
    const int b_n   = n0 + (lane & 7) + ((lane & 16) ? 8 : 0);
    const uint32_t b_lane_off = (uint32_t)b_n * WROWB + ((lane & 8) ? 16 : 0);

    float acc[2][2][4];

    // ---- 3 pipelined stages: one matrix each, full K=128, single bf16 pass ----
    for (int s = 0; s < 3; ++s) {
        CP_WAIT0();
        __syncthreads();

        if (s < 2) {   // prefetch next matrix into the other buffer
            const __nv_bfloat16* wsrc = g_whi + (size_t)(h * 3 + s + 1) * 16384;
            const uint32_t dbuf = sbase + SM_WB + ((s + 1) & 1) * WBUF_SZ;
            #pragma unroll
            for (int j = 0; j < 4; ++j) {
                int c = tid + j * 512;
                int r = c >> 4, ch = c & 15;
                cp_async16(dbuf + r * WROWB + ch * 16, wsrc + (size_t)r * 128 + ch * 8);
            }
            CP_COMMIT();
        }

        #pragma unroll
        for (int a = 0; a < 2; ++a)
            #pragma unroll
            for (int b = 0; b < 2; ++b)
                #pragma unroll
                for (int c = 0; c < 4; ++c) acc[a][b][c] = 0.f;

        const uint32_t buf = sbase + SM_WB + (s & 1) * WBUF_SZ;

        #pragma unroll
        for (int ktl = 0; ktl < 8; ++ktl) {
            const int k0 = ktl * 16;
            uint32_t A[2][4];
            #pragma unroll
            for (int Mt = 0; Mt < 2; ++Mt) {
                const uint32_t aoff =
                    (uint32_t)((mg * 32 + Mt * 16 + a_row) * XPITCH + k0 + a_kof) * 2;
                ldm_x4(A[Mt][0], A[Mt][1], A[Mt][2], A[Mt][3], sbase + SM_XHI + aoff);
            }
            uint32_t Bf[2][2];
            ldm_x4(Bf[0][0], Bf[0][1], Bf[1][0], Bf[1][1],
                   buf + b_lane_off + (uint32_t)k0 * 2);
            #pragma unroll
            for (int Mt = 0; Mt < 2; ++Mt)
                #pragma unroll
                for (int Nt = 0; Nt < 2; ++Nt)
                    mma_bf16(acc[Mt][Nt], A[Mt][0], A[Mt][1], A[Mt][2], A[Mt][3],
                             Bf[Nt][0], Bf[Nt][1]);
        }

        {   // write q/k/v tile
            float* dst = (float*)(smem + SM_QKV) + (size_t)s * NB * QPITCH;
            #pragma unroll
            for (int Mt = 0; Mt < 2; ++Mt)
                #pragma unroll
                for (int Nt = 0; Nt < 2; ++Nt) {
                    int r = mg * 32 + Mt * 16 + g;
                    int c = n0 + Nt * 8 + 2 * tg;
                    dst[r * QPITCH + c]           = acc[Mt][Nt][0];
                    dst[r * QPITCH + c + 1]       = acc[Mt][Nt][1];
                    dst[(r + 8) * QPITCH + c]     = acc[Mt][Nt][2];
                    dst[(r + 8) * QPITCH + c + 1] = acc[Mt][Nt][3];
                }
        }
    }
    __syncthreads();

    // ================= epilogue: separable moment softmax =================
    const float* q_s = (const float*)(smem + SM_QKV);
    const float* k_s = q_s + NB * QPITCH;
    const float* v_s = q_s + 2 * NB * QPITCH;
    float* red  = (float*)(smem + SM_RED);
    float* coef = (float*)(smem + SM_COEF);
    float* outs = (float*)(smem + SM_OUTS);

    {   // Phase A: k/v moment partials over 16 e's  +  fp32 S0 GEMV partial over 16 d's
        const int b = tid & 63, part = tid >> 6;
        float K1=0,K2=0,K3=0,K4=0,K5=0,K6=0;
        float S1=0,S2=0,S3=0,S4=0,S5=0,S6=0;
        #pragma unroll
        for (int i = 0; i < 16; ++i) {
            int e = part * 16 + i;
            float kv = k_s[b * QPITCH + e];   // = k * SCALE (folded in conv)
            float vv = v_s[b * QPITCH + e];
            float t = kv; K1 += t; S1 = fmaf(t, vv, S1);
            t *= kv;      K2 += t; S2 = fmaf(t, vv, S2);
            t *= kv;      K3 += t; S3 = fmaf(t, vv, S3);
            t *= kv;      K4 += t; S4 = fmaf(t, vv, S4);
            t *= kv;      K5 += t; S5 = fmaf(t, vv, S5);
            t *= kv;      K6 += t; S6 = fmaf(t, vv, S6);
        }
        // exact S0 partial: sum_d x[b][d] * wvsum[d]   (x = xh + xl, fp32-accurate)
        float S0 = 0.f;
        {
            const __nv_bfloat16* xh = (const __nv_bfloat16*)(smem + SM_XHI) + b * XPITCH;
            const __nv_bfloat16* xl = (const __nv_bfloat16*)(smem + SM_XLO) + b * XPITCH;
            const float* wv = g_wvsum + h * 128 + part * 16;
            #pragma unroll
            for (int i = 0; i < 16; ++i) {
                int d = part * 16 + i;
                float xv = __bfloat162float(xh[d]) + __bfloat162float(xl[d]);
                S0 = fmaf(xv, __ldg(&wv[i]), S0);
            }
        }
        float* rr = red + ((size_t)part * 64 + b) * 13;
        rr[0]=K1; rr[1]=K2; rr[2]=K3; rr[3]=K4; rr[4]=K5; rr[5]=K6;
        rr[6]=S0; rr[7]=S1; rr[8]=S2; rr[9]=S3; rr[10]=S4; rr[11]=S5; rr[12]=S6;
    }
    __syncthreads();

    if (tid < 64) {   // Phase B: combine + fold 1/n!
        float c[13];
        #pragma unroll
        for (int j = 0; j < 13; ++j) c[j] = 0.f;
        #pragma unroll
        for (int p = 0; p < 8; ++p) {
            const float* rr = red + ((size_t)p * 64 + tid) * 13;
            #pragma unroll
            for (int j = 0; j < 13; ++j) c[j] += rr[j];
        }
        float* cc = coef + tid * 13;
        cc[0] = c[0];               cc[1] = c[1] * 0.5f;
        cc[2] = c[2] * (1.f/6.f);   cc[3] = c[3] * (1.f/24.f);
        cc[4] = c[4] * (1.f/120.f); cc[5] = c[5] * (1.f/720.f);
        cc[6] = c[6];               cc[7] = c[7];
        cc[8] = c[8] * 0.5f;        cc[9] = c[9] * (1.f/6.f);
        cc[10]= c[10]* (1.f/24.f);  cc[11]= c[11]* (1.f/120.f);
        cc[12]= c[12]* (1.f/720.f);
    }
    __syncthreads();

    {   // Phase C: Horner
        const int b = tid & 63, part = tid >> 6;
        const float* cc = coef + b * 13;
        const float a1=cc[0],a2=cc[1],a3=cc[2],a4=cc[3],a5=cc[4],a6=cc[5];
        const float g0=cc[6],g1=cc[7],g2=cc[8],g3=cc[9],g4=cc[10],g5=cc[11],g6=cc[12];
        #pragma unroll
        for (int i = 0; i < 16; ++i) {
            int d = part * 16 + i;
            float q = q_s[b * QPITCH + d];
            float den = fmaf(a6, q, a5);
            den = fmaf(den, q, a4); den = fmaf(den, q, a3);
            den = fmaf(den, q, a2); den = fmaf(den, q, a1);
            den = fmaf(den, q, 128.0f);
            float num = fmaf(g6, q, g5);
            num = fmaf(num, q, g4); num = fmaf(num, q, g3);
            num = fmaf(num, q, g2); num = fmaf(num, q, g1);
            num = fmaf(num, q, g0);
            outs[b * QPITCH + d] = num * rcpf(den);
        }
    }
    __syncthreads();

    {   // coalesced copy out
        const int b = tid >> 3, ds = (tid & 7) * 16;
        float* dst = out + (size_t)(b0 + b) * CDIM + h * HD + ds;
        #pragma unroll
        for (int j = 0; j < 4; ++j) {
            float4 v;
            v.x = outs[b * QPITCH + ds + j*4 + 0];
            v.y = outs[b * QPITCH + ds + j*4 + 1];
            v.z = outs[b * QPITCH + ds + j*4 + 2];
            v.w = outs[b * QPITCH + ds + j*4 + 3];
            *(float4*)(dst + j*4) = v;
        }
    }
}

extern "C" void kernel_launch(void* const* d_in, const int* in_sizes, int n_in,
                              void* d_out, int out_size) {
    const float* x   = (const float*)d_in[0];
    const float* Wq  = (const float*)d_in[1];
    const float* Wkv = (const float*)d_in[2];
    float* out = (float*)d_out;

    conv_kernel<<<392, 256>>>(Wq, Wkv);

    cudaFuncSetAttribute(satt_kernel, cudaFuncAttributeMaxDynamicSharedMemorySize, SM_TOTAL);
    dim3 grid(BSZ / NB, NHEAD);
    satt_kernel<<<grid, THREADS, SM_TOTAL>>>(x, out);
}